// round 5
// baseline (speedup 1.0000x reference)
#include <cuda_runtime.h>
#include <cuda_bf16.h>
#include <cuda_fp16.h>

#define NCI 16
#define NCO 32
#define NBR 3
#define NTERM (NCI * 9 * NBR)   // 432 per co
#define HH 32
#define WW 32
#define NBATCH 4

__device__ __forceinline__ __half2 tanh2_approx(__half2 x) {
    unsigned xi = *(unsigned*)&x;
    unsigned yi;
    asm("tanh.approx.f16x2 %0, %1;" : "=r"(yi) : "r"(xi));
    return *(__half2*)&yi;
}

// Block = (b, co, 4-row tile). 128 threads = 2 ci-groups x 64 threads.
// Each thread: 2 vertically adjacent pixels, 8 of 16 input channels.
// Entire basis evaluation in f16x2 (pixel pair packed); f32 accumulation.
__global__ __launch_bounds__(128, 7)
void ferro_main_kernel(const float* __restrict__ x,
                       const float* __restrict__ k,
                       const float* __restrict__ Ec,
                       const float* __restrict__ Ps,
                       const float* __restrict__ bias,
                       const float* __restrict__ coef,
                       const float* __restrict__ out_bias,
                       float* __restrict__ out) {
    __shared__ uint4  sA[NTERM];        // {h2(5Ec), h2(k), h2(0.9kEc), h2(0.1kEc)} dup'd
    __shared__ float  sC[NTERM];        // coef*Ps (f32)
    __shared__ float  sx[NCI][6][34];   // 6 input rows, 34 cols (zero padded)
    __shared__ float  sP[64][2];        // group-1 partials
    __shared__ float  sRed[4];

    int tid  = threadIdx.x;
    int tile = blockIdx.x & 7;          // 8 tiles of 4 output rows
    int co   = (blockIdx.x >> 3) & 31;
    int b    = blockIdx.x >> 8;
    int r0   = tile * 4;

    // ---- stage x tile: 16 ci x 6 rows x 8 float4 = 768 float4 (6 per thread)
    #pragma unroll
    for (int i = 0; i < 6; i++) {
        int idx = tid + i * 128;
        int c4  = idx & 7;
        int rr  = (idx >> 3) % 6;
        int ci  = idx / 48;
        int gr  = r0 - 1 + rr;
        float4 v = make_float4(0.f, 0.f, 0.f, 0.f);
        if ((unsigned)gr < 32u)
            v = *(const float4*)(x + (((b * NCI + ci) * HH + gr) * WW) + c4 * 4);
        int cb0 = c4 * 4 + 1;
        sx[ci][rr][cb0 + 0] = v.x;
        sx[ci][rr][cb0 + 1] = v.y;
        sx[ci][rr][cb0 + 2] = v.z;
        sx[ci][rr][cb0 + 3] = v.w;
    }
    if (tid < 96) {                     // zero the pad columns
        int ci = tid / 6, rr = tid % 6;
        sx[ci][rr][0]  = 0.0f;
        sx[ci][rr][33] = 0.0f;
    }

    // ---- pack params for this co (432 terms = 108 float4 groups)
    float cb = 0.0f;
    if (tid < NTERM / 4) {
        const float4* k4 = (const float4*)(k    + co * NTERM);
        const float4* e4 = (const float4*)(Ec   + co * NTERM);
        const float4* p4 = (const float4*)(Ps   + co * NTERM);
        const float4* b4 = (const float4*)(bias + co * NTERM);
        const float4* c4 = (const float4*)(coef + co * NTERM);
        float4 kk = k4[tid], ee = e4[tid], pp = p4[tid], bb = b4[tid], cc = c4[tid];
        float kkv[4] = {kk.x, kk.y, kk.z, kk.w};
        float eev[4] = {ee.x, ee.y, ee.z, ee.w};
        float ppv[4] = {pp.x, pp.y, pp.z, pp.w};
        float bbv[4] = {bb.x, bb.y, bb.z, bb.w};
        float ccv[4] = {cc.x, cc.y, cc.z, cc.w};
        #pragma unroll
        for (int j = 0; j < 4; j++) {
            float ke = kkv[j] * eev[j];
            __half2 e5 = __float2half2_rn(5.0f * eev[j]);
            __half2 kh = __float2half2_rn(kkv[j]);
            __half2 z9 = __float2half2_rn(0.9f * ke);
            __half2 w1 = __float2half2_rn(0.1f * ke);
            uint4 u;
            u.x = *(unsigned*)&e5;
            u.y = *(unsigned*)&kh;
            u.z = *(unsigned*)&z9;
            u.w = *(unsigned*)&w1;
            sA[tid * 4 + j] = u;
            sC[tid * 4 + j] = ccv[j] * ppv[j];
            cb += ccv[j] * bbv[j];
        }
    }
    // block-reduce cb (position-independent term)
    #pragma unroll
    for (int s = 16; s > 0; s >>= 1)
        cb += __shfl_xor_sync(0xFFFFFFFFu, cb, s);
    if ((tid & 31) == 0) sRed[tid >> 5] = cb;
    __syncthreads();
    float bc = (sRed[0] + sRed[1]) + (sRed[2] + sRed[3]) + out_bias[co];

    int cig = tid >> 6;       // ci-group: 0 or 1 (8 channels each)
    int t   = tid & 63;
    int wo  = t & 31;         // output col
    int lr  = t >> 5;         // 0..1 -> rows r0+2lr, r0+2lr+1

    const __half2 FIVE2 = __float2half2_rn(5.0f);

    float acc[6] = {0.f, 0.f, 0.f, 0.f, 0.f, 0.f};

    #pragma unroll 1
    for (int ci8 = 0; ci8 < 8; ci8++) {
        int ci = cig * 8 + ci8;
        // 4 input rows x 3 cols shared by the vertical pixel pair
        float xv[12];
        #pragma unroll
        for (int r = 0; r < 4; r++)
            #pragma unroll
            for (int c = 0; c < 3; c++)
                xv[r * 3 + c] = sx[ci][2 * lr + r][wo + c];
        // pack pixel-pair half2 per tap: low = pixel0 (rows dy), high = pixel1 (rows dy+1)
        __half2 xh[9];
        #pragma unroll
        for (int dy = 0; dy < 3; dy++)
            #pragma unroll
            for (int dx = 0; dx < 3; dx++)
                xh[dy * 3 + dx] = __floats2half2_rn(xv[dy * 3 + dx], xv[(dy + 1) * 3 + dx]);

        const uint4* pa = &sA[ci * 27];
        const float* pc = &sC[ci * 27];
        #pragma unroll
        for (int nb = 0; nb < NBR; nb++) {
            #pragma unroll
            for (int ij = 0; ij < 9; ij++) {
                uint4 u  = pa[nb * 9 + ij];
                float cp = pc[nb * 9 + ij];
                __half2 e5 = *(__half2*)&u.x;
                __half2 kh = *(__half2*)&u.y;
                __half2 z9 = *(__half2*)&u.z;
                __half2 w1 = *(__half2*)&u.w;
                __half2 xp = xh[ij];
                // t1 = tanh(5x + 5Ec)
                __half2 t1 = tanh2_approx(__hfma2(xp, FIVE2, e5));
                // arg2 = k*x + 0.9kEc + 0.1kEc*t1
                __half2 g    = __hfma2(xp, kh, z9);
                __half2 t2   = tanh2_approx(__hfma2(t1, w1, g));
                float t20 = __low2float(t2);
                float t21 = __high2float(t2);
                acc[nb * 2 + 0] = fmaf(cp, t20, acc[nb * 2 + 0]);
                acc[nb * 2 + 1] = fmaf(cp, t21, acc[nb * 2 + 1]);
            }
        }
    }

    float r0v = (acc[0] + acc[2]) + acc[4];
    float r1v = (acc[1] + acc[3]) + acc[5];

    if (cig == 1) {
        sP[t][0] = r0v;
        sP[t][1] = r1v;
    }
    __syncthreads();
    if (cig == 0) {
        int ho = r0 + 2 * lr;
        float* op = out + (((b * NCO + co) * HH + ho) * WW) + wo;
        op[0]  = (r0v + sP[t][0]) + bc;
        op[WW] = (r1v + sP[t][1]) + bc;
    }
}

extern "C" void kernel_launch(void* const* d_in, const int* in_sizes, int n_in,
                              void* d_out, int out_size) {
    const float* x        = (const float*)d_in[0];
    const float* k        = (const float*)d_in[1];
    const float* Ec       = (const float*)d_in[2];
    const float* Ps       = (const float*)d_in[3];
    const float* bias     = (const float*)d_in[4];
    const float* coef     = (const float*)d_in[5];
    const float* out_bias = (const float*)d_in[6];
    float* out = (float*)d_out;

    ferro_main_kernel<<<NBATCH * NCO * 8, 128>>>(x, k, Ec, Ps, bias, coef, out_bias, out);
}

// round 6
// speedup vs baseline: 1.0421x; 1.0421x over previous
#include <cuda_runtime.h>
#include <cuda_bf16.h>
#include <cuda_fp16.h>

#define NCI 16
#define NCO 32
#define NBR 3
#define NTERM (NCI * 9 * NBR)   // 432 per co
#define HH 32
#define WW 32
#define NBATCH 4

__device__ __forceinline__ __half2 tanh2_approx(__half2 x) {
    unsigned xi = *(unsigned*)&x;
    unsigned yi;
    asm("tanh.approx.f16x2 %0, %1;" : "=r"(yi) : "r"(xi));
    return *(__half2*)&yi;
}

// Block = (b, co, 4-row tile). 128 threads = 2 ci-groups x 64 threads.
// Each thread: 2 vertically adjacent pixels, 8 of 16 input channels.
// x tile stored in smem as vertical-pair half2; all basis math f16x2.
__global__ __launch_bounds__(128, 9)
void ferro_main_kernel(const float* __restrict__ x,
                       const float* __restrict__ k,
                       const float* __restrict__ Ec,
                       const float* __restrict__ Ps,
                       const float* __restrict__ bias,
                       const float* __restrict__ coef,
                       const float* __restrict__ out_bias,
                       float* __restrict__ out) {
    __shared__ uint4   sA[NTERM];         // {h2(5Ec), h2(k), h2(0.9kEc), h2(0.1kEc)}
    __shared__ float   sC[NTERM];         // coef*Ps (f32)
    __shared__ __half2 sxp[NCI][5][34];   // vertical-pair rows, zero padded cols
    __shared__ float   sP[64][2];         // group-1 partials
    __shared__ float   sRed[4];

    int tid  = threadIdx.x;
    int tile = blockIdx.x & 7;            // 8 tiles of 4 output rows
    int co   = (blockIdx.x >> 3) & 31;
    int b    = blockIdx.x >> 8;
    int r0   = tile * 4;

    // ---- stage x tile as vertical-pair half2: 16 ci x 5 rr x 8 col-groups = 640
    #pragma unroll
    for (int i = 0; i < 5; i++) {
        int idx = tid + i * 128;
        int c4  = idx & 7;
        int rr  = (idx >> 3) % 5;
        int ci  = idx / 40;
        int g0  = r0 - 1 + rr;            // pixel-0 tap row
        int g1  = r0 + rr;                // pixel-1 tap row
        const float* base = x + ((b * NCI + ci) * HH) * WW + c4 * 4;
        float4 v0 = make_float4(0.f, 0.f, 0.f, 0.f);
        float4 v1 = make_float4(0.f, 0.f, 0.f, 0.f);
        if ((unsigned)g0 < 32u) v0 = *(const float4*)(base + g0 * WW);
        if ((unsigned)g1 < 32u) v1 = *(const float4*)(base + g1 * WW);
        int cb0 = c4 * 4 + 1;
        sxp[ci][rr][cb0 + 0] = __floats2half2_rn(v0.x, v1.x);
        sxp[ci][rr][cb0 + 1] = __floats2half2_rn(v0.y, v1.y);
        sxp[ci][rr][cb0 + 2] = __floats2half2_rn(v0.z, v1.z);
        sxp[ci][rr][cb0 + 3] = __floats2half2_rn(v0.w, v1.w);
    }
    if (tid < 80) {                       // zero pad columns: 16 ci x 5 rr
        int ci = tid / 5, rr = tid % 5;
        sxp[ci][rr][0]  = __float2half2_rn(0.f);
        sxp[ci][rr][33] = __float2half2_rn(0.f);
    }

    // ---- pack params for this co (432 terms = 108 float4 groups)
    float cb = 0.0f;
    if (tid < NTERM / 4) {
        const float4* k4 = (const float4*)(k    + co * NTERM);
        const float4* e4 = (const float4*)(Ec   + co * NTERM);
        const float4* p4 = (const float4*)(Ps   + co * NTERM);
        const float4* b4 = (const float4*)(bias + co * NTERM);
        const float4* c4 = (const float4*)(coef + co * NTERM);
        float4 kk = k4[tid], ee = e4[tid], pp = p4[tid], bb = b4[tid], cc = c4[tid];
        float kkv[4] = {kk.x, kk.y, kk.z, kk.w};
        float eev[4] = {ee.x, ee.y, ee.z, ee.w};
        float ppv[4] = {pp.x, pp.y, pp.z, pp.w};
        float bbv[4] = {bb.x, bb.y, bb.z, bb.w};
        float ccv[4] = {cc.x, cc.y, cc.z, cc.w};
        #pragma unroll
        for (int j = 0; j < 4; j++) {
            float ke = kkv[j] * eev[j];
            __half2 e5 = __float2half2_rn(5.0f * eev[j]);
            __half2 kh = __float2half2_rn(kkv[j]);
            __half2 z9 = __float2half2_rn(0.9f * ke);
            __half2 w1 = __float2half2_rn(0.1f * ke);
            uint4 u;
            u.x = *(unsigned*)&e5;
            u.y = *(unsigned*)&kh;
            u.z = *(unsigned*)&z9;
            u.w = *(unsigned*)&w1;
            sA[tid * 4 + j] = u;
            sC[tid * 4 + j] = ccv[j] * ppv[j];
            cb += ccv[j] * bbv[j];
        }
    }
    // block-reduce cb (position-independent term)
    #pragma unroll
    for (int s = 16; s > 0; s >>= 1)
        cb += __shfl_xor_sync(0xFFFFFFFFu, cb, s);
    if ((tid & 31) == 0) sRed[tid >> 5] = cb;
    __syncthreads();
    float bc = (sRed[0] + sRed[1]) + (sRed[2] + sRed[3]) + out_bias[co];

    int cig = tid >> 6;       // ci-group: 0 or 1 (8 channels each)
    int t   = tid & 63;
    int wo  = t & 31;         // output col
    int lr  = t >> 5;         // 0..1 -> rows r0+2lr, r0+2lr+1

    const __half2 FIVE2 = __float2half2_rn(5.0f);

    float acc[6] = {0.f, 0.f, 0.f, 0.f, 0.f, 0.f};

    #pragma unroll 1
    for (int ci8 = 0; ci8 < 8; ci8++) {
        int ci = cig * 8 + ci8;
        // 9 taps, both pixels packed: xh = {x[p0 tap], x[p1 tap]}
        __half2 xh[9];
        #pragma unroll
        for (int dy = 0; dy < 3; dy++)
            #pragma unroll
            for (int dx = 0; dx < 3; dx++)
                xh[dy * 3 + dx] = sxp[ci][2 * lr + dy][wo + dx];

        const uint4* pa = &sA[ci * 27];
        const float* pc = &sC[ci * 27];
        #pragma unroll
        for (int nb = 0; nb < NBR; nb++) {
            #pragma unroll
            for (int ij = 0; ij < 9; ij++) {
                uint4 u  = pa[nb * 9 + ij];
                float cp = pc[nb * 9 + ij];
                __half2 e5 = *(__half2*)&u.x;
                __half2 kh = *(__half2*)&u.y;
                __half2 z9 = *(__half2*)&u.z;
                __half2 w1 = *(__half2*)&u.w;
                __half2 xp = xh[ij];
                __half2 g  = __hfma2(xp, kh, z9);             // overlaps MUFU-1
                __half2 t1 = tanh2_approx(__hfma2(xp, FIVE2, e5));
                __half2 t2 = tanh2_approx(__hfma2(t1, w1, g));
                float t20 = __low2float(t2);
                float t21 = __high2float(t2);
                acc[nb * 2 + 0] = fmaf(cp, t20, acc[nb * 2 + 0]);
                acc[nb * 2 + 1] = fmaf(cp, t21, acc[nb * 2 + 1]);
            }
        }
    }

    float r0v = (acc[0] + acc[2]) + acc[4];
    float r1v = (acc[1] + acc[3]) + acc[5];

    if (cig == 1) {
        sP[t][0] = r0v;
        sP[t][1] = r1v;
    }
    __syncthreads();
    if (cig == 0) {
        int ho = r0 + 2 * lr;
        float* op = out + (((b * NCO + co) * HH + ho) * WW) + wo;
        op[0]  = (r0v + sP[t][0]) + bc;
        op[WW] = (r1v + sP[t][1]) + bc;
    }
}

extern "C" void kernel_launch(void* const* d_in, const int* in_sizes, int n_in,
                              void* d_out, int out_size) {
    const float* x        = (const float*)d_in[0];
    const float* k        = (const float*)d_in[1];
    const float* Ec       = (const float*)d_in[2];
    const float* Ps       = (const float*)d_in[3];
    const float* bias     = (const float*)d_in[4];
    const float* coef     = (const float*)d_in[5];
    const float* out_bias = (const float*)d_in[6];
    float* out = (float*)d_out;

    ferro_main_kernel<<<NBATCH * NCO * 8, 128>>>(x, k, Ec, Ps, bias, coef, out_bias, out);
}